// round 2
// baseline (speedup 1.0000x reference)
#include <cuda_runtime.h>
#include <cuda_bf16.h>

// ---------------------------------------------------------------------------
// DQN_19198503813318 — R2: channel-pair packed fp32 via PTX fma.rn.f32x2.
// Activations+weights live in SMEM as float2 (even ic in .x, odd ic in .y);
// every MAC is one FFMA2 (2 FMAs/lane) -> 2x the scalar FFMA roofline.
// ---------------------------------------------------------------------------

#define BL 3072

__device__ float g_s0[BL * 32 * 21 * 21];   // after stage0 (planar)
__device__ float g_s1[BL * 32 * 9 * 9];     // after stage1
__device__ float g_s2[BL * 64 * 4 * 4];     // after stage2
__device__ float g_s3[BL * 256];            // flattened features

__device__ __forceinline__ float prelu(float v, float a) {
    return v >= 0.0f ? v : a * v;
}

__device__ __forceinline__ float2 ffma2(float2 a, float2 b, float2 c) {
    float2 d;
    asm("fma.rn.f32x2 %0, %1, %2, %3;"
        : "=l"(reinterpret_cast<unsigned long long&>(d))
        : "l"(reinterpret_cast<unsigned long long&>(a)),
          "l"(reinterpret_cast<unsigned long long&>(b)),
          "l"(reinterpret_cast<unsigned long long&>(c)));
    return d;
}

// ---------------------------------------------------------------------------
// Stage 0: conv(4->32, 5x5, pad1) + prelu + pool2   in: x (BL,4,45,45)
// grid = BL, block = 224 (oc = tid&31, g = tid>>5 in 0..6)
// smem: sIn2[2 icp][46][46] float2 + sW2[32 oc][51] float2 (icp*25+k)
// ---------------------------------------------------------------------------
#define C0_IN2 (2 * 46 * 46)      // 4232 float2
#define C0_W2  (32 * 51)          // 1632 float2
__global__ void k_conv0(const float* __restrict__ x,
                        const float* __restrict__ w,
                        const float* __restrict__ b,
                        const float* __restrict__ ap) {
    extern __shared__ __align__(16) float smemf[];
    float2* sIn2 = (float2*)smemf;
    float2* sW2  = sIn2 + C0_IN2;
    float*  fIn  = (float*)sIn2;
    float*  fW   = (float*)sW2;
    const int bl  = blockIdx.x;
    const int tid = threadIdx.x;

    for (int i = tid; i < C0_IN2 * 2; i += 224) fIn[i] = 0.0f;
    __syncthreads();
    const float* xb = x + bl * 8100;
    for (int i = tid; i < 8100; i += 224) {
        int ic = i / 2025;
        int r  = (i / 45) % 45;
        int c  = i % 45;
        fIn[((ic >> 1) * 2116 + (r + 1) * 46 + (c + 1)) * 2 + (ic & 1)] = xb[i];
    }
    for (int k = tid; k < 3200; k += 224) {
        int oc = k / 100;
        int ic = (k % 100) / 25;
        int kk = k % 25;
        fW[(oc * 51 + (ic >> 1) * 25 + kk) * 2 + (ic & 1)] = w[k];
    }
    __syncthreads();

    const int oc = tid & 31;
    const int g  = tid >> 5;            // 0..6
    const float bias = b[oc];
    const float a = *ap;
    const float2* wB = sW2 + oc * 51;

    for (int py = 0; py < 21; ++py) {
        float2 accA[6], accB[6];
#pragma unroll
        for (int j = 0; j < 6; ++j) {
            accA[j] = make_float2(0.f, 0.f);
            accB[j] = make_float2(0.f, 0.f);
        }
        const int y0 = 2 * py;
#pragma unroll
        for (int icp = 0; icp < 2; ++icp) {
            const float2* inC = sIn2 + icp * 2116;
#pragma unroll
            for (int ky = 0; ky < 5; ++ky) {
                const float2* r0 = inC + (y0 + ky) * 46 + 6 * g;
                const float2* r1 = r0 + 46;
                float2 ra[10], rb[10];
#pragma unroll
                for (int j = 0; j < 10; ++j) { ra[j] = r0[j]; rb[j] = r1[j]; }
                const float2* wv = wB + icp * 25 + ky * 5;
#pragma unroll
                for (int kx = 0; kx < 5; ++kx) {
                    float2 wk = wv[kx];
#pragma unroll
                    for (int j = 0; j < 6; ++j) {
                        accA[j] = ffma2(ra[j + kx], wk, accA[j]);
                        accB[j] = ffma2(rb[j + kx], wk, accB[j]);
                    }
                }
            }
        }
        float* o = g_s0 + ((bl * 32 + oc) * 21 + py) * 21 + 3 * g;
#pragma unroll
        for (int u = 0; u < 3; ++u) {
            float v0 = prelu(accA[2 * u].x + accA[2 * u].y + bias, a);
            float v1 = prelu(accA[2 * u + 1].x + accA[2 * u + 1].y + bias, a);
            float v2 = prelu(accB[2 * u].x + accB[2 * u].y + bias, a);
            float v3 = prelu(accB[2 * u + 1].x + accB[2 * u + 1].y + bias, a);
            o[u] = fmaxf(fmaxf(v0, v1), fmaxf(v2, v3));
        }
    }
}

// ---------------------------------------------------------------------------
// Stage 1: conv(32->32, 5x5, pad1) + prelu + pool2   in: g_s0 (BL,32,21,21)
// grid = (BL,2), block = 432 (ocl = tid&15, py=(tid>>4)%9, g=tid/144)
// smem: sIn2[16 icp][22][22] float2 + sW2[16 ocl][401] float2 (icp*25+k)
// ---------------------------------------------------------------------------
#define C1_IN2 (16 * 484)        // 7744 float2
#define C1_W2  (16 * 401)        // 6416 float2
__global__ void k_conv1(const float* __restrict__ w,
                        const float* __restrict__ b,
                        const float* __restrict__ ap) {
    extern __shared__ __align__(16) float smemf[];
    float2* sIn2 = (float2*)smemf;
    float2* sW2  = sIn2 + C1_IN2;
    float*  fIn  = (float*)sIn2;
    float*  fW   = (float*)sW2;
    const int bl   = blockIdx.x;
    const int half = blockIdx.y;
    const int tid  = threadIdx.x;

    for (int i = tid; i < C1_IN2 * 2; i += 432) fIn[i] = 0.0f;
    __syncthreads();
    const float* src = g_s0 + bl * (32 * 441);
    for (int i = tid; i < 32 * 441; i += 432) {
        int ic = i / 441;
        int r  = (i / 21) % 21;
        int c  = i % 21;
        fIn[((ic >> 1) * 484 + (r + 1) * 22 + (c + 1)) * 2 + (ic & 1)] = src[i];
    }
    for (int k = tid; k < 16 * 800; k += 432) {
        int ocl = k / 800;
        int rem = k % 800;          // ic*25 + kk
        int ic  = rem / 25;
        int kk  = rem % 25;
        fW[(ocl * 401 + (ic >> 1) * 25 + kk) * 2 + (ic & 1)] =
            w[(half * 16 + ocl) * 800 + rem];
    }
    __syncthreads();

    const int ocl = tid & 15;
    const int py  = (tid >> 4) % 9;
    const int g   = tid / 144;       // 0..2
    const int oc  = half * 16 + ocl;
    const float bias = b[oc];
    const float a = *ap;
    const float2* wB = sW2 + ocl * 401;

    float2 accA[6], accB[6];
#pragma unroll
    for (int j = 0; j < 6; ++j) {
        accA[j] = make_float2(0.f, 0.f);
        accB[j] = make_float2(0.f, 0.f);
    }
    const int y0 = 2 * py;
    for (int icp = 0; icp < 16; ++icp) {
        const float2* inC = sIn2 + icp * 484;
#pragma unroll
        for (int ky = 0; ky < 5; ++ky) {
            const float2* r0 = inC + (y0 + ky) * 22 + 6 * g;
            const float2* r1 = r0 + 22;
            float2 ra[10], rb[10];
#pragma unroll
            for (int j = 0; j < 10; ++j) { ra[j] = r0[j]; rb[j] = r1[j]; }
            const float2* wv = wB + icp * 25 + ky * 5;
#pragma unroll
            for (int kx = 0; kx < 5; ++kx) {
                float2 wk = wv[kx];
#pragma unroll
                for (int j = 0; j < 6; ++j) {
                    accA[j] = ffma2(ra[j + kx], wk, accA[j]);
                    accB[j] = ffma2(rb[j + kx], wk, accB[j]);
                }
            }
        }
    }
    float* o = g_s1 + ((bl * 32 + oc) * 9 + py) * 9 + 3 * g;
#pragma unroll
    for (int u = 0; u < 3; ++u) {
        float v0 = prelu(accA[2 * u].x + accA[2 * u].y + bias, a);
        float v1 = prelu(accA[2 * u + 1].x + accA[2 * u + 1].y + bias, a);
        float v2 = prelu(accB[2 * u].x + accB[2 * u].y + bias, a);
        float v3 = prelu(accB[2 * u + 1].x + accB[2 * u + 1].y + bias, a);
        o[u] = fmaxf(fmaxf(v0, v1), fmaxf(v2, v3));
    }
}

// ---------------------------------------------------------------------------
// Stage 2: conv(32->64, 4x4, pad1) + prelu + pool2   in: g_s1 (BL,32,9,9)
// grid = (BL,2), block = 512 (ocl = tid&31, p=tid>>5: py=p>>2 px=p&3)
// smem: sIn2[16 icp][11][12] float2 + sW2[32 ocl][257] float2 (icp*16+k)
// ---------------------------------------------------------------------------
#define C2_IN2 (16 * 132)        // 2112 float2
#define C2_W2  (32 * 257)        // 8224 float2
__global__ void k_conv2(const float* __restrict__ w,
                        const float* __restrict__ b,
                        const float* __restrict__ ap) {
    extern __shared__ __align__(16) float smemf[];
    float2* sIn2 = (float2*)smemf;
    float2* sW2  = sIn2 + C2_IN2;
    float*  fIn  = (float*)sIn2;
    float*  fW   = (float*)sW2;
    const int bl   = blockIdx.x;
    const int half = blockIdx.y;
    const int tid  = threadIdx.x;

    for (int i = tid; i < C2_IN2 * 2; i += 512) fIn[i] = 0.0f;
    __syncthreads();
    const float* src = g_s1 + bl * (32 * 81);
    for (int i = tid; i < 32 * 81; i += 512) {
        int ic = i / 81;
        int r  = (i / 9) % 9;
        int c  = i % 9;
        fIn[((ic >> 1) * 132 + (r + 1) * 12 + (c + 1)) * 2 + (ic & 1)] = src[i];
    }
    for (int k = tid; k < 32 * 512; k += 512) {
        int ocl = k >> 9;
        int rem = k & 511;          // ic*16 + kk
        int ic  = rem >> 4;
        int kk  = rem & 15;
        fW[(ocl * 257 + (ic >> 1) * 16 + kk) * 2 + (ic & 1)] =
            w[(half * 32 + ocl) * 512 + rem];
    }
    __syncthreads();

    const int ocl = tid & 31;
    const int p   = tid >> 5;
    const int py  = p >> 2;
    const int px  = p & 3;
    const int oc  = half * 32 + ocl;
    const float bias = b[oc];
    const float a = *ap;
    const float2* wB = sW2 + ocl * 257;

    float2 accA[2], accB[2];
    accA[0] = accA[1] = accB[0] = accB[1] = make_float2(0.f, 0.f);
    for (int icp = 0; icp < 16; ++icp) {
        const float2* inC = sIn2 + icp * 132;
#pragma unroll
        for (int ky = 0; ky < 4; ++ky) {
            const float2* r0 = inC + (2 * py + ky) * 12 + 2 * px;
            const float2* r1 = r0 + 12;
            float2 ra[5], rb[5];
#pragma unroll
            for (int j = 0; j < 5; ++j) { ra[j] = r0[j]; rb[j] = r1[j]; }
            const float2* wv = wB + icp * 16 + ky * 4;
#pragma unroll
            for (int kx = 0; kx < 4; ++kx) {
                float2 wk = wv[kx];
                accA[0] = ffma2(ra[kx],     wk, accA[0]);
                accA[1] = ffma2(ra[kx + 1], wk, accA[1]);
                accB[0] = ffma2(rb[kx],     wk, accB[0]);
                accB[1] = ffma2(rb[kx + 1], wk, accB[1]);
            }
        }
    }
    float v0 = prelu(accA[0].x + accA[0].y + bias, a);
    float v1 = prelu(accA[1].x + accA[1].y + bias, a);
    float v2 = prelu(accB[0].x + accB[0].y + bias, a);
    float v3 = prelu(accB[1].x + accB[1].y + bias, a);
    g_s2[((bl * 64 + oc) * 4 + py) * 4 + px] = fmaxf(fmaxf(v0, v1), fmaxf(v2, v3));
}

// ---------------------------------------------------------------------------
// Stage 3: conv(64->64, 3x3, pad0) + prelu + flatten  in: g_s2 (BL,64,4,4)
// grid = 384 (8 images/block), block = 256 (oc = tid>>2, pos = tid&3)
// smem: sW2[64 oc][289] float2 (icp*9+k) + sIn2[8 img][32 icp][16] float2
// ---------------------------------------------------------------------------
#define C3_W2  (64 * 289)        // 18496 float2
#define C3_IN2 (8 * 512)         // 4096 float2
__global__ void k_conv3(const float* __restrict__ w,
                        const float* __restrict__ b,
                        const float* __restrict__ ap) {
    extern __shared__ __align__(16) float smemf[];
    float2* sW2  = (float2*)smemf;
    float2* sIn2 = sW2 + C3_W2;
    float*  fW   = (float*)sW2;
    float*  fIn  = (float*)sIn2;
    const int tid = threadIdx.x;
    const int bl0 = blockIdx.x * 8;

    for (int k = tid; k < 64 * 576; k += 256) {
        int oc  = k / 576;
        int rem = k % 576;          // ic*9 + kk
        int ic  = rem / 9;
        int kk  = rem % 9;
        fW[(oc * 289 + (ic >> 1) * 9 + kk) * 2 + (ic & 1)] = w[k];
    }
    const float* src = g_s2 + bl0 * 1024;
    for (int i = tid; i < 8192; i += 256) {
        int img = i >> 10;
        int ic  = (i >> 4) & 63;
        int pos = i & 15;
        fIn[((img * 512) + (ic >> 1) * 16 + pos) * 2 + (ic & 1)] = src[i];
    }
    __syncthreads();

    const int oc  = tid >> 2;
    const int pos = tid & 3;
    const int yy  = pos >> 1;
    const int xx  = pos & 1;
    const float bias = b[oc];
    const float a = *ap;

    float2 acc[8];
#pragma unroll
    for (int i = 0; i < 8; ++i) acc[i] = make_float2(0.f, 0.f);

    for (int icp = 0; icp < 32; ++icp) {
        const float2* wv = sW2 + oc * 289 + icp * 9;
        float2 wr[9];
#pragma unroll
        for (int j = 0; j < 9; ++j) wr[j] = wv[j];
#pragma unroll
        for (int img = 0; img < 8; ++img) {
            const float2* ip = sIn2 + img * 512 + icp * 16;
#pragma unroll
            for (int ky = 0; ky < 3; ++ky)
#pragma unroll
                for (int kx = 0; kx < 3; ++kx)
                    acc[img] = ffma2(ip[(yy + ky) * 4 + (xx + kx)], wr[ky * 3 + kx], acc[img]);
        }
    }
#pragma unroll
    for (int img = 0; img < 8; ++img) {
        g_s3[(bl0 + img) * 256 + oc * 4 + pos] = prelu(acc[img].x + acc[img].y + bias, a);
    }
}

// ---------------------------------------------------------------------------
// FC heads: per (b,l): 256 -> 128 (prelu a4[l]) -> 64 (prelu a5[l]) -> 4
// grid = BL, block = 128
// ---------------------------------------------------------------------------
__global__ void k_fc(const float* __restrict__ fc1_w, const float* __restrict__ fc1_b,
                     const float* __restrict__ a4,
                     const float* __restrict__ fc2_w, const float* __restrict__ fc2_b,
                     const float* __restrict__ a5,
                     const float* __restrict__ fc3_w, const float* __restrict__ fc3_b,
                     float* __restrict__ out) {
    __shared__ float feat[256];
    __shared__ float h1[128];
    __shared__ float h2[64];
    const int bl  = blockIdx.x;
    const int l   = bl % 6;
    const int tid = threadIdx.x;

    feat[tid]       = g_s3[bl * 256 + tid];
    feat[tid + 128] = g_s3[bl * 256 + 128 + tid];
    __syncthreads();

    {
        float acc = fc1_b[l * 128 + tid];
        const float* W = fc1_w + l * 256 * 128 + tid;
#pragma unroll 8
        for (int i = 0; i < 256; ++i) acc = fmaf(feat[i], W[i * 128], acc);
        float av = a4[l];
        h1[tid] = prelu(acc, av);
    }
    __syncthreads();
    if (tid < 64) {
        float acc = fc2_b[l * 64 + tid];
        const float* W = fc2_w + l * 128 * 64 + tid;
#pragma unroll 8
        for (int i = 0; i < 128; ++i) acc = fmaf(h1[i], W[i * 64], acc);
        float av = a5[l];
        h2[tid] = prelu(acc, av);
    }
    __syncthreads();
    if (tid < 4) {
        float acc = fc3_b[l * 4 + tid];
        const float* W = fc3_w + l * 64 * 4 + tid;
#pragma unroll
        for (int i = 0; i < 64; ++i) acc = fmaf(h2[i], W[i * 4], acc);
        out[bl * 4 + tid] = acc;
    }
}

// ---------------------------------------------------------------------------
extern "C" void kernel_launch(void* const* d_in, const int* in_sizes, int n_in,
                              void* d_out, int out_size) {
    const float* x     = (const float*)d_in[0];
    const float* w0    = (const float*)d_in[1];
    const float* b0    = (const float*)d_in[2];
    const float* w1    = (const float*)d_in[3];
    const float* b1    = (const float*)d_in[4];
    const float* w2    = (const float*)d_in[5];
    const float* b2    = (const float*)d_in[6];
    const float* w3    = (const float*)d_in[7];
    const float* b3    = (const float*)d_in[8];
    const float* a0    = (const float*)d_in[9];
    const float* a1    = (const float*)d_in[10];
    const float* a2    = (const float*)d_in[11];
    const float* a3    = (const float*)d_in[12];
    const float* fc1_w = (const float*)d_in[13];
    const float* fc1_b = (const float*)d_in[14];
    const float* a4    = (const float*)d_in[15];
    const float* fc2_w = (const float*)d_in[16];
    const float* fc2_b = (const float*)d_in[17];
    const float* a5    = (const float*)d_in[18];
    const float* fc3_w = (const float*)d_in[19];
    const float* fc3_b = (const float*)d_in[20];
    float* out = (float*)d_out;

    const int smem0 = (C0_IN2 + C0_W2) * 8;   // 46,912 B
    const int smem1 = (C1_IN2 + C1_W2) * 8;   // 113,280 B
    const int smem2 = (C2_IN2 + C2_W2) * 8;   // 82,688 B
    const int smem3 = (C3_W2 + C3_IN2) * 8;   // 180,736 B

    cudaFuncSetAttribute(k_conv0, cudaFuncAttributeMaxDynamicSharedMemorySize, smem0);
    cudaFuncSetAttribute(k_conv1, cudaFuncAttributeMaxDynamicSharedMemorySize, smem1);
    cudaFuncSetAttribute(k_conv2, cudaFuncAttributeMaxDynamicSharedMemorySize, smem2);
    cudaFuncSetAttribute(k_conv3, cudaFuncAttributeMaxDynamicSharedMemorySize, smem3);

    k_conv0<<<BL, 224, smem0>>>(x, w0, b0, a0);
    k_conv1<<<dim3(BL, 2), 432, smem1>>>(w1, b1, a1);
    k_conv2<<<dim3(BL, 2), 512, smem2>>>(w2, b2, a2);
    k_conv3<<<BL / 8, 256, smem3>>>(w3, b3, a3);
    k_fc<<<BL, 128>>>(fc1_w, fc1_b, a4, fc2_w, fc2_b, a5, fc3_w, fc3_b, out);
}

// round 4
// speedup vs baseline: 1.1500x; 1.1500x over previous
#include <cuda_runtime.h>
#include <cuda_bf16.h>
#include <cstdint>

// ---------------------------------------------------------------------------
// DQN_19198503813318 — R4: conv1 via mma.sync (tf32 m16n8k8, hi/lo x3 split).
// tcgen05 is uncompilable on this toolchain (PTX target sm_103 without 'a');
// mma.sync is baseline PTX and runs on the tensor pipe as HMMA.
// conv0/conv2/conv3/fc remain scalar (at the FFMA roofline).
// ---------------------------------------------------------------------------

#define BL 3072

__device__ float g_s0[BL * 32 * 21 * 21];   // after stage0 (planar)
__device__ float g_s1[BL * 32 * 9 * 9];     // after stage1
__device__ float g_s2[BL * 64 * 4 * 4];     // after stage2
__device__ float g_s3[BL * 256];            // flattened features
// conv1 weights, per (p, icq): [32 lanes][16 floats]
//   lane l, slot s: nf = s>>2, which = s&3 (0:hi k, 1:hi k+4, 2:lo k, 3:lo k+4)
//   n = nf*8 + (l>>2), k = icq*8 + (l&3) + (which&1)*4
__device__ float g_w1B[25 * 4 * 32 * 16];

__device__ __forceinline__ float prelu(float v, float a) {
    return v >= 0.0f ? v : a * v;
}

__device__ __forceinline__ uint32_t tf32_hi(float v) {
    uint32_t h;
    asm("cvt.rna.tf32.f32 %0, %1;" : "=r"(h) : "f"(v));
    return h;
}

__device__ __forceinline__ void mma_tf32(float4& d,
                                         uint32_t a0, uint32_t a1, uint32_t a2, uint32_t a3,
                                         uint32_t b0, uint32_t b1) {
    asm volatile(
        "mma.sync.aligned.m16n8k8.row.col.f32.tf32.tf32.f32 "
        "{%0,%1,%2,%3}, {%4,%5,%6,%7}, {%8,%9}, {%0,%1,%2,%3};"
        : "+f"(d.x), "+f"(d.y), "+f"(d.z), "+f"(d.w)
        : "r"(a0), "r"(a1), "r"(a2), "r"(a3), "r"(b0), "r"(b1));
}

// ---------------------------------------------------------------------------
// conv1 weight prep: split tf32 hi/lo into per-fragment LDG.128 groups.
// grid = (25, 4) [p, icq], block = 512 (l = tid>>4, s = tid&15)
// ---------------------------------------------------------------------------
__global__ void k_w1prep(const float* __restrict__ w1) {
    const int p   = blockIdx.x;
    const int icq = blockIdx.y;
    const int tid = threadIdx.x;
    const int l   = tid >> 4;
    const int s   = tid & 15;
    const int nf    = s >> 2;
    const int which = s & 3;
    const int n = nf * 8 + (l >> 2);
    const int k = icq * 8 + (l & 3) + (which & 1) * 4;
    float v = w1[n * 800 + k * 25 + p];
    float hi = __uint_as_float(tf32_hi(v));
    float outv;
    if (which < 2) outv = hi;
    else           outv = __uint_as_float(tf32_hi(v - hi));
    g_w1B[(((p * 4 + icq) * 32) + l) * 16 + s] = outv;
}

// ---------------------------------------------------------------------------
// Stage 1 (tensor mma.sync): conv(32->32,5x5,pad1)+prelu+pool2
// grid = BL, block = 224 (7 warps x 3 M-tiles of 16 rows = 21 tiles = 336>=324)
// smem: imgCL[23*23 rows][33] channel-last padded image; reused as stage buf.
// ---------------------------------------------------------------------------
#define IMG_F (529 * 33)
#define SMEM_C1 (IMG_F * 4)

__global__ void __launch_bounds__(224)
k_conv1_mma(const float* __restrict__ b, const float* __restrict__ ap) {
    extern __shared__ float imgCL[];
    const int tid = threadIdx.x;
    const int wid = tid >> 5;
    const int lid = tid & 31;
    const int bl  = blockIdx.x;

    for (int i = tid; i < IMG_F; i += 224) imgCL[i] = 0.0f;
    __syncthreads();
    const float* src = g_s0 + bl * 14112;
    for (int i = tid; i < 14112; i += 224) {
        int ic  = i / 441;
        int pix = i - ic * 441;
        int y   = pix / 21;
        int x   = pix - y * 21;
        imgCL[((y + 1) * 23 + (x + 1)) * 33 + ic] = src[i];
    }
    __syncthreads();

    // per-warp tile setup: tiles 3w..3w+2, rows m = tile*16 + (lid>>2) (+8)
    int base[3][2];
#pragma unroll
    for (int t = 0; t < 3; ++t) {
#pragma unroll
        for (int j = 0; j < 2; ++j) {
            int m  = (wid * 3 + t) * 16 + (lid >> 2) + j * 8;
            int mm = m < 324 ? m : 0;
            int ym = mm / 18;
            int xm = mm - ym * 18;
            base[t][j] = (ym * 23 + xm) * 33;
        }
    }

    float4 acc[3][4];
#pragma unroll
    for (int t = 0; t < 3; ++t)
#pragma unroll
        for (int nf = 0; nf < 4; ++nf)
            acc[t][nf] = make_float4(0.f, 0.f, 0.f, 0.f);

    const int cbase = lid & 3;
    for (int p = 0; p < 25; ++p) {
        const int ky = p / 5;
        const int kx = p - ky * 5;
        const int off_p = (ky * 23 + kx) * 33;
#pragma unroll
        for (int icq = 0; icq < 4; ++icq) {
            // B fragments: 4 x LDG.128 (hi k, hi k+4, lo k, lo k+4) per nfrag
            const float4* gB = (const float4*)(g_w1B + (((p * 4 + icq) * 32) + lid) * 16);
            float4 B0 = gB[0], B1 = gB[1], B2 = gB[2], B3 = gB[3];
            const int c = icq * 8 + cbase;
#pragma unroll
            for (int t = 0; t < 3; ++t) {
                float v00 = imgCL[base[t][0] + off_p + c];
                float v10 = imgCL[base[t][1] + off_p + c];
                float v01 = imgCL[base[t][0] + off_p + c + 4];
                float v11 = imgCL[base[t][1] + off_p + c + 4];
                uint32_t h00 = tf32_hi(v00), h10 = tf32_hi(v10);
                uint32_t h01 = tf32_hi(v01), h11 = tf32_hi(v11);
                uint32_t l00 = tf32_hi(v00 - __uint_as_float(h00));
                uint32_t l10 = tf32_hi(v10 - __uint_as_float(h10));
                uint32_t l01 = tf32_hi(v01 - __uint_as_float(h01));
                uint32_t l11 = tf32_hi(v11 - __uint_as_float(h11));
                // pass1: Ahi * Bhi ; pass2: Alo * Bhi ; pass3: Ahi * Blo
                mma_tf32(acc[t][0], h00, h10, h01, h11,
                         __float_as_uint(B0.x), __float_as_uint(B0.y));
                mma_tf32(acc[t][0], l00, l10, l01, l11,
                         __float_as_uint(B0.x), __float_as_uint(B0.y));
                mma_tf32(acc[t][0], h00, h10, h01, h11,
                         __float_as_uint(B0.z), __float_as_uint(B0.w));
                mma_tf32(acc[t][1], h00, h10, h01, h11,
                         __float_as_uint(B1.x), __float_as_uint(B1.y));
                mma_tf32(acc[t][1], l00, l10, l01, l11,
                         __float_as_uint(B1.x), __float_as_uint(B1.y));
                mma_tf32(acc[t][1], h00, h10, h01, h11,
                         __float_as_uint(B1.z), __float_as_uint(B1.w));
                mma_tf32(acc[t][2], h00, h10, h01, h11,
                         __float_as_uint(B2.x), __float_as_uint(B2.y));
                mma_tf32(acc[t][2], l00, l10, l01, l11,
                         __float_as_uint(B2.x), __float_as_uint(B2.y));
                mma_tf32(acc[t][2], h00, h10, h01, h11,
                         __float_as_uint(B2.z), __float_as_uint(B2.w));
                mma_tf32(acc[t][3], h00, h10, h01, h11,
                         __float_as_uint(B3.x), __float_as_uint(B3.y));
                mma_tf32(acc[t][3], l00, l10, l01, l11,
                         __float_as_uint(B3.x), __float_as_uint(B3.y));
                mma_tf32(acc[t][3], h00, h10, h01, h11,
                         __float_as_uint(B3.z), __float_as_uint(B3.w));
            }
        }
    }
    __syncthreads();   // image no longer needed; reuse imgCL as stage buffer

    // stage: bias + prelu, rows m (0..335) x 32 oc, stride 33
    const float a = *ap;
    float* stage = imgCL;
    {
        const int r0 = (wid * 3) * 16 + (lid >> 2);   // tile t adds t*16
        const int oc0 = 2 * (lid & 3);
#pragma unroll
        for (int t = 0; t < 3; ++t) {
            int ra = r0 + t * 16;
            int rb = ra + 8;
#pragma unroll
            for (int nf = 0; nf < 4; ++nf) {
                int ca = nf * 8 + oc0;
                float ba = b[ca], bb = b[ca + 1];
                stage[ra * 33 + ca]     = prelu(acc[t][nf].x + ba, a);
                stage[ra * 33 + ca + 1] = prelu(acc[t][nf].y + bb, a);
                stage[rb * 33 + ca]     = prelu(acc[t][nf].z + ba, a);
                stage[rb * 33 + ca + 1] = prelu(acc[t][nf].w + bb, a);
            }
        }
    }
    __syncthreads();

    // 2x2 maxpool -> planar g_s1 (BL,32,9,9)
    float* out = g_s1 + bl * 2592;
    for (int i = tid; i < 2592; i += 224) {
        int oc = i / 81;
        int pp = i - oc * 81;
        int py = pp / 9;
        int px = pp - py * 9;
        int m00 = (2 * py) * 18 + 2 * px;
        float v = fmaxf(fmaxf(stage[m00 * 33 + oc],        stage[(m00 + 1) * 33 + oc]),
                        fmaxf(stage[(m00 + 18) * 33 + oc], stage[(m00 + 19) * 33 + oc]));
        out[i] = v;
    }
}

// ---------------------------------------------------------------------------
// Stage 0 (scalar): conv(4->32,5x5,pad1)+prelu+pool2
// ---------------------------------------------------------------------------
__global__ void k_conv0(const float* __restrict__ x,
                        const float* __restrict__ w,
                        const float* __restrict__ b,
                        const float* __restrict__ ap) {
    extern __shared__ float smem[];
    float* sIn = smem;          // 4*46*46 = 8464
    float* sW  = smem + 8464;   // 32*101  = 3232
    const int bl  = blockIdx.x;
    const int tid = threadIdx.x;

    for (int i = tid; i < 8464; i += 224) sIn[i] = 0.0f;
    __syncthreads();
    const float* xb = x + bl * 8100;
    for (int i = tid; i < 8100; i += 224) {
        int ic = i / 2025;
        int r  = (i / 45) % 45;
        int c  = i % 45;
        sIn[ic * 2116 + (r + 1) * 46 + (c + 1)] = xb[i];
    }
    for (int k = tid; k < 3200; k += 224) {
        int oc = k / 100;
        sW[oc * 101 + (k % 100)] = w[k];
    }
    __syncthreads();

    const int oc = tid & 31;
    const int g  = tid >> 5;
    const float bias = b[oc];
    const float a = *ap;
    const float* wB = sW + oc * 101;

    for (int py = 0; py < 21; ++py) {
        float accA[6], accB[6];
#pragma unroll
        for (int j = 0; j < 6; ++j) { accA[j] = bias; accB[j] = bias; }
        const int y0 = 2 * py;
        for (int ic = 0; ic < 4; ++ic) {
            const float* inC = sIn + ic * 2116;
#pragma unroll
            for (int ky = 0; ky < 5; ++ky) {
                const float* r0 = inC + (y0 + ky) * 46 + 6 * g;
                const float* r1 = r0 + 46;
                float ra[10], rb[10];
#pragma unroll
                for (int j = 0; j < 10; ++j) { ra[j] = r0[j]; rb[j] = r1[j]; }
                const float* wv = wB + ic * 25 + ky * 5;
#pragma unroll
                for (int kx = 0; kx < 5; ++kx) {
                    float wk = wv[kx];
#pragma unroll
                    for (int j = 0; j < 6; ++j) {
                        accA[j] = fmaf(ra[j + kx], wk, accA[j]);
                        accB[j] = fmaf(rb[j + kx], wk, accB[j]);
                    }
                }
            }
        }
        float* o = g_s0 + ((bl * 32 + oc) * 21 + py) * 21 + 3 * g;
#pragma unroll
        for (int u = 0; u < 3; ++u) {
            float v0 = prelu(accA[2 * u], a);
            float v1 = prelu(accA[2 * u + 1], a);
            float v2 = prelu(accB[2 * u], a);
            float v3 = prelu(accB[2 * u + 1], a);
            o[u] = fmaxf(fmaxf(v0, v1), fmaxf(v2, v3));
        }
    }
}

// ---------------------------------------------------------------------------
// Stage 2 (scalar): conv(32->64,4x4,pad1)+prelu+pool2
// ---------------------------------------------------------------------------
__global__ void k_conv2(const float* __restrict__ w,
                        const float* __restrict__ b,
                        const float* __restrict__ ap) {
    extern __shared__ float smem[];
    float* sIn = smem;            // 32*132 = 4224
    float* sW  = smem + 4224;     // 32*513 = 16416
    const int bl   = blockIdx.x;
    const int half = blockIdx.y;
    const int tid  = threadIdx.x;

    for (int i = tid; i < 4224; i += 512) sIn[i] = 0.0f;
    __syncthreads();
    const float* src = g_s1 + bl * (32 * 81);
    for (int i = tid; i < 32 * 81; i += 512) {
        int ic = i / 81;
        int r  = (i / 9) % 9;
        int c  = i % 9;
        sIn[ic * 132 + (r + 1) * 12 + (c + 1)] = src[i];
    }
    for (int k = tid; k < 32 * 512; k += 512) {
        int ocl = k >> 9;
        sW[ocl * 513 + (k & 511)] = w[(half * 32 + ocl) * 512 + (k & 511)];
    }
    __syncthreads();

    const int ocl = tid & 31;
    const int p   = tid >> 5;
    const int py  = p >> 2;
    const int px  = p & 3;
    const int oc  = half * 32 + ocl;
    const float bias = b[oc];
    const float a = *ap;
    const float* wB = sW + ocl * 513;

    float accA[2], accB[2];
    accA[0] = accA[1] = accB[0] = accB[1] = bias;
    for (int ic = 0; ic < 32; ++ic) {
        const float* inC = sIn + ic * 132;
#pragma unroll
        for (int ky = 0; ky < 4; ++ky) {
            const float* r0 = inC + (2 * py + ky) * 12 + 2 * px;
            const float* r1 = r0 + 12;
            float ra[5], rb[5];
#pragma unroll
            for (int j = 0; j < 5; ++j) { ra[j] = r0[j]; rb[j] = r1[j]; }
            const float* wv = wB + ic * 16 + ky * 4;
#pragma unroll
            for (int kx = 0; kx < 4; ++kx) {
                float wk = wv[kx];
                accA[0] = fmaf(ra[kx],     wk, accA[0]);
                accA[1] = fmaf(ra[kx + 1], wk, accA[1]);
                accB[0] = fmaf(rb[kx],     wk, accB[0]);
                accB[1] = fmaf(rb[kx + 1], wk, accB[1]);
            }
        }
    }
    float v0 = prelu(accA[0], a);
    float v1 = prelu(accA[1], a);
    float v2 = prelu(accB[0], a);
    float v3 = prelu(accB[1], a);
    g_s2[((bl * 64 + oc) * 4 + py) * 4 + px] = fmaxf(fmaxf(v0, v1), fmaxf(v2, v3));
}

// ---------------------------------------------------------------------------
// Stage 3 (scalar): conv(64->64,3x3,pad0)+prelu+flatten
// ---------------------------------------------------------------------------
__global__ void k_conv3(const float* __restrict__ w,
                        const float* __restrict__ b,
                        const float* __restrict__ ap) {
    extern __shared__ float smem[];
    float* sW  = smem;             // 64*577 = 36928
    float* sIn = smem + 36928;     // 8*1024 = 8192
    const int tid = threadIdx.x;
    const int bl0 = blockIdx.x * 8;

    for (int k = tid; k < 64 * 576; k += 256) {
        int oc = k / 576;
        sW[oc * 577 + (k % 576)] = w[k];
    }
    const float* src = g_s2 + bl0 * 1024;
    for (int i = tid; i < 8192; i += 256) sIn[i] = src[i];
    __syncthreads();

    const int oc  = tid >> 2;
    const int pos = tid & 3;
    const int yy  = pos >> 1;
    const int xx  = pos & 1;
    const float bias = b[oc];
    const float a = *ap;

    float acc[8];
#pragma unroll
    for (int i = 0; i < 8; ++i) acc[i] = bias;

    for (int ic = 0; ic < 64; ++ic) {
        const float* wv = sW + oc * 577 + ic * 9;
        float wr[9];
#pragma unroll
        for (int j = 0; j < 9; ++j) wr[j] = wv[j];
#pragma unroll
        for (int img = 0; img < 8; ++img) {
            const float* ip = sIn + img * 1024 + ic * 16;
#pragma unroll
            for (int ky = 0; ky < 3; ++ky)
#pragma unroll
                for (int kx = 0; kx < 3; ++kx)
                    acc[img] = fmaf(ip[(yy + ky) * 4 + (xx + kx)], wr[ky * 3 + kx], acc[img]);
        }
    }
#pragma unroll
    for (int img = 0; img < 8; ++img) {
        g_s3[(bl0 + img) * 256 + oc * 4 + pos] = prelu(acc[img], a);
    }
}

// ---------------------------------------------------------------------------
// FC heads
// ---------------------------------------------------------------------------
__global__ void k_fc(const float* __restrict__ fc1_w, const float* __restrict__ fc1_b,
                     const float* __restrict__ a4,
                     const float* __restrict__ fc2_w, const float* __restrict__ fc2_b,
                     const float* __restrict__ a5,
                     const float* __restrict__ fc3_w, const float* __restrict__ fc3_b,
                     float* __restrict__ out) {
    __shared__ float feat[256];
    __shared__ float h1[128];
    __shared__ float h2[64];
    const int bl  = blockIdx.x;
    const int l   = bl % 6;
    const int tid = threadIdx.x;

    feat[tid]       = g_s3[bl * 256 + tid];
    feat[tid + 128] = g_s3[bl * 256 + 128 + tid];
    __syncthreads();

    {
        float acc = fc1_b[l * 128 + tid];
        const float* W = fc1_w + l * 256 * 128 + tid;
#pragma unroll 8
        for (int i = 0; i < 256; ++i) acc = fmaf(feat[i], W[i * 128], acc);
        float av = a4[l];
        h1[tid] = prelu(acc, av);
    }
    __syncthreads();
    if (tid < 64) {
        float acc = fc2_b[l * 64 + tid];
        const float* W = fc2_w + l * 128 * 64 + tid;
#pragma unroll 8
        for (int i = 0; i < 128; ++i) acc = fmaf(h1[i], W[i * 64], acc);
        float av = a5[l];
        h2[tid] = prelu(acc, av);
    }
    __syncthreads();
    if (tid < 4) {
        float acc = fc3_b[l * 4 + tid];
        const float* W = fc3_w + l * 64 * 4 + tid;
#pragma unroll
        for (int i = 0; i < 64; ++i) acc = fmaf(h2[i], W[i * 4], acc);
        out[bl * 4 + tid] = acc;
    }
}

// ---------------------------------------------------------------------------
extern "C" void kernel_launch(void* const* d_in, const int* in_sizes, int n_in,
                              void* d_out, int out_size) {
    const float* x     = (const float*)d_in[0];
    const float* w0    = (const float*)d_in[1];
    const float* b0    = (const float*)d_in[2];
    const float* w1    = (const float*)d_in[3];
    const float* b1    = (const float*)d_in[4];
    const float* w2    = (const float*)d_in[5];
    const float* b2    = (const float*)d_in[6];
    const float* w3    = (const float*)d_in[7];
    const float* b3    = (const float*)d_in[8];
    const float* a0    = (const float*)d_in[9];
    const float* a1    = (const float*)d_in[10];
    const float* a2    = (const float*)d_in[11];
    const float* a3    = (const float*)d_in[12];
    const float* fc1_w = (const float*)d_in[13];
    const float* fc1_b = (const float*)d_in[14];
    const float* a4    = (const float*)d_in[15];
    const float* fc2_w = (const float*)d_in[16];
    const float* fc2_b = (const float*)d_in[17];
    const float* a5    = (const float*)d_in[18];
    const float* fc3_w = (const float*)d_in[19];
    const float* fc3_b = (const float*)d_in[20];
    float* out = (float*)d_out;

    const int smem0 = (8464 + 3232) * 4;
    const int smem2 = (4224 + 16416) * 4;
    const int smem3 = (36928 + 8192) * 4;

    cudaFuncSetAttribute(k_conv0, cudaFuncAttributeMaxDynamicSharedMemorySize, smem0);
    cudaFuncSetAttribute(k_conv1_mma, cudaFuncAttributeMaxDynamicSharedMemorySize, SMEM_C1);
    cudaFuncSetAttribute(k_conv2, cudaFuncAttributeMaxDynamicSharedMemorySize, smem2);
    cudaFuncSetAttribute(k_conv3, cudaFuncAttributeMaxDynamicSharedMemorySize, smem3);

    k_w1prep<<<dim3(25, 4), 512>>>(w1);
    k_conv0<<<BL, 224, smem0>>>(x, w0, b0, a0);
    k_conv1_mma<<<BL, 224, SMEM_C1>>>(b1, a1);
    k_conv2<<<dim3(BL, 2), 512, smem2>>>(w2, b2, a2);
    k_conv3<<<BL / 8, 256, smem3>>>(w3, b3, a3);
    k_fc<<<BL, 128>>>(fc1_w, fc1_b, a4, fc2_w, fc2_b, a5, fc3_w, fc3_b, out);
}